// round 12
// baseline (speedup 1.0000x reference)
#include <cuda_runtime.h>
#include <cuda_fp16.h>
#include <cstddef>

// Digits_Caps dynamic routing. B=32, C=8192, U=32, K=16, I=16, 3 iters.
// Unified HMMA GEMM kernel, 3 passes over channels:
//  PASS 0: read W fp32, write W fp16 scratch, s~1 = sum_c u_hat (HMMA)
//  PASS 1: recompute u_hat from fp16 W, a->b (b_old=0, write bij), weighted s~2
//  PASS 2: same but b_old from bij (no write), weighted s~3
// u_hat is NEVER materialized (saves 256MB wr + 512MB rd vs R11).

#define NSTRIPE 152
#define ELEMS 16384   // B*U*K

// fp16 W scratch: [(c*16+w)*128 + f] 8-byte units = 128 MB
static __device__ uint2 g_w16[(size_t)8192 * 16 * 128];
static __device__ float g_spart[NSTRIPE * ELEMS];
static __device__ float g_zpart[NSTRIPE * 32];
static __device__ float g_sred[ELEMS];
static __device__ float g_zred[32];
static __device__ float g_v[ELEMS];
static __device__ float g_bij[8192 * 32];

__device__ __forceinline__ unsigned packh2(float lo, float hi) {
  unsigned r;
  asm("cvt.rn.f16x2.f32 %0, %1, %2;" : "=r"(r) : "f"(hi), "f"(lo));
  return r;
}
__device__ __forceinline__ unsigned smem_u32(const void* p) {
  unsigned a;
  asm("{ .reg .u64 t; cvta.to.shared.u64 t, %1; cvt.u32.u64 %0, t; }"
      : "=r"(a) : "l"(p));
  return a;
}
__device__ __forceinline__ void sts64(unsigned addr, unsigned p0, unsigned p1) {
  asm volatile("st.shared.v2.b32 [%0], {%1, %2};" :: "r"(addr), "r"(p0), "r"(p1));
}
__device__ __forceinline__ unsigned lds32(unsigned addr) {
  unsigned v;
  asm("ld.shared.b32 %0, [%1];" : "=r"(v) : "r"(addr));
  return v;
}
__device__ __forceinline__ void ldmatrix_x4(unsigned& r0, unsigned& r1,
                                            unsigned& r2, unsigned& r3,
                                            unsigned addr) {
  asm volatile("ldmatrix.sync.aligned.m8n8.x4.shared.b16 {%0,%1,%2,%3}, [%4];"
               : "=r"(r0), "=r"(r1), "=r"(r2), "=r"(r3) : "r"(addr));
}
__device__ __forceinline__ void mma16816(float& d0, float& d1, float& d2, float& d3,
                                         unsigned a0, unsigned a1, unsigned a2, unsigned a3,
                                         unsigned b0, unsigned b1) {
  asm volatile(
      "mma.sync.aligned.m16n8k16.row.col.f32.f16.f16.f32 "
      "{%0,%1,%2,%3}, {%4,%5,%6,%7}, {%8,%9}, {%10,%11,%12,%13};"
      : "=f"(d0), "=f"(d1), "=f"(d2), "=f"(d3)
      : "r"(a0), "r"(a1), "r"(a2), "r"(a3), "r"(b0), "r"(b1),
        "f"(0.f), "f"(0.f), "f"(0.f), "f"(0.f));
}

// smem: x16 [j=0..7][b=0..31 rows of 48B][i*2] then per-warp W16 buf (32t x 48B)
#define XCH 1536
#define WAOFF 12288
#define WBUF 1536
#define SM_TOT (WAOFF + 16 * WBUF)   // 36864 B (static)

// ---------------- unified GEMM + routing pass -----------------------------
template <int PASS>
__global__ __launch_bounds__(512, 1) void gemm_kernel(
    const float* __restrict__ x, const float* __restrict__ W) {
  __shared__ __align__(128) char sm[SM_TOT];
  const int t = threadIdx.x;
  const int w = t >> 5;            // warp 0..15, owns t-range [w*32, w*32+32)
  const int ln = t & 31;
  const int gid = ln >> 2;         // 0..7
  const int tig = ln & 3;          // 0..3
  const int bid = blockIdx.x;

  const unsigned xb = smem_u32(sm);
  const unsigned wbuf = xb + WAOFF + w * WBUF;

  const unsigned lrow = (ln & 7) + ((ln >> 3) & 1) * 8;
  const unsigned lcol = (ln >> 4) * 16;

  float sacc[32];
#pragma unroll
  for (int p = 0; p < 32; p++) sacc[p] = 0.f;
  float accz0 = 0.f, accz1 = 0.f;

  // v in registers (PASS>=1): vv[m*16+T*4+q] matching d-fragment layout
  float vv[32];
  if (PASS >= 1) {
#pragma unroll
    for (int m = 0; m < 2; m++)
#pragma unroll
      for (int T = 0; T < 4; T++) {
        const int t0 = w * 32 + m * 16 + gid;
        const int b0 = T * 8 + 2 * tig;
        vv[m * 16 + T * 4 + 0] = g_v[(size_t)b0 * 512 + t0];
        vv[m * 16 + T * 4 + 1] = g_v[(size_t)(b0 + 1) * 512 + t0];
        vv[m * 16 + T * 4 + 2] = g_v[(size_t)b0 * 512 + t0 + 8];
        vv[m * 16 + T * 4 + 3] = g_v[(size_t)(b0 + 1) * 512 + t0 + 8];
      }
  }

  // ---- warp-private W staging ---------------------------------------------
  // packed regs pk[2r],pk[2r+1] hold 8 halfs at f = ln + r*32 (f in 32t x 16i slice)
  auto load_pk = [&](int c, unsigned* pk) {
    if (PASS == 0) {
      const float4* src = (const float4*)(W + (size_t)c * 8192 + w * 512);
#pragma unroll
      for (int r = 0; r < 4; r++) {
        const float4 v = src[ln + r * 32];
        pk[2 * r]     = packh2(v.x, v.y);
        pk[2 * r + 1] = packh2(v.z, v.w);
      }
    } else {
      const uint2* src = g_w16 + ((size_t)c * 16 + w) * 128;
#pragma unroll
      for (int r = 0; r < 4; r++) {
        const uint2 v = src[ln + r * 32];
        pk[2 * r] = v.x; pk[2 * r + 1] = v.y;
      }
    }
  };
  auto store_pk = [&](int c, const unsigned* pk) {
    if (PASS == 0) {
      uint2* dst = g_w16 + ((size_t)c * 16 + w) * 128;
#pragma unroll
      for (int r = 0; r < 4; r++) {
        uint2 v; v.x = pk[2 * r]; v.y = pk[2 * r + 1];
        dst[ln + r * 32] = v;
      }
    }
#pragma unroll
    for (int r = 0; r < 4; r++) {
      const int f = ln + r * 32;
      sts64(wbuf + (f >> 2) * 48 + (f & 3) * 8, pk[2 * r], pk[2 * r + 1]);
    }
  };

  // preload first channel
  {
    unsigned pk[8];
    load_pk(bid * 8, pk);
    store_pk(bid * 8, pk);
  }

  for (int chunk = bid; chunk < 1024; chunk += NSTRIPE) {
    __syncthreads();   // previous chunk's compute done with x16
    const int cbase = chunk * 8;
#pragma unroll
    for (int r = 0; r < 8; r++) {
      const int e = t + r * 512;
      const int j = e & 7, bi = e >> 3;
      const int i = bi & 15, b = bi >> 4;
      const float v = x[(size_t)bi * 8192 + cbase + j];
      *(__half*)(sm + j * XCH + b * 48 + i * 2) = __float2half(v);
    }
    __syncthreads();

#pragma unroll 1
    for (int j = 0; j < 8; j++) {
      const int c = cbase + j;
      const int cn = (j < 7) ? (c + 1) : (chunk + NSTRIPE) * 8;

      // prefetch next channel's W into registers (latency hidden by compute)
      unsigned pk[8];
      if (cn < 8192) load_pk(cn, pk);

      // B fragments from x16[j]
      unsigned bf[8];
#pragma unroll
      for (int T = 0; T < 4; T++) {
        const unsigned ba = xb + j * XCH + (T * 8 + gid) * 48 + tig * 4;
        bf[2 * T]     = lds32(ba);
        bf[2 * T + 1] = lds32(ba + 16);
      }

#pragma unroll
      for (int m = 0; m < 2; m++) {
        unsigned a0, a1, a2, a3;
        ldmatrix_x4(a0, a1, a2, a3, wbuf + (m * 16 + lrow) * 48 + lcol);

        float dm[16];
#pragma unroll
        for (int T = 0; T < 4; T++)
          mma16816(dm[T * 4], dm[T * 4 + 1], dm[T * 4 + 2], dm[T * 4 + 3],
                   a0, a1, a2, a3, bf[2 * T], bf[2 * T + 1]);

        if (PASS == 0) {
#pragma unroll
          for (int p = 0; p < 16; p++) sacc[m * 16 + p] += dm[p];
        } else {
          // a[c,u] partial: dot(u_hat, v) over this lane's (k,b) coverage
          float part = 0.f;
#pragma unroll
          for (int p = 0; p < 16; p++) part = fmaf(dm[p], vv[m * 16 + p], part);
          // full-warp butterfly: sums over all 16 k and 32 b of u = 2w+m
#pragma unroll
          for (int o = 16; o > 0; o >>= 1)
            part += __shfl_xor_sync(0xffffffffu, part, o);

          const float a = part * (1.f / 32.f);
          const int bidx = c * 32 + 2 * w + m;
          const float bnew = (PASS == 1) ? a : (g_bij[bidx] + a);
          if (PASS == 1 && ln == 0) g_bij[bidx] = bnew;
          const float wt = __expf(bnew);
          if (m == 0) accz0 += wt; else accz1 += wt;
#pragma unroll
          for (int p = 0; p < 16; p++)
            sacc[m * 16 + p] = fmaf(wt, dm[p], sacc[m * 16 + p]);
        }
      }

      // stage next channel into the (now-free) warp-private buffer
      if (cn < 8192) store_pk(cn, pk);
      __syncwarp();
    }
  }

  // s~ partials -> g_spart[bid][b*512 + t]
  float* gp = g_spart + (size_t)bid * ELEMS;
#pragma unroll
  for (int m = 0; m < 2; m++)
#pragma unroll
    for (int T = 0; T < 4; T++) {
      const int t0 = w * 32 + m * 16 + gid;
      const int b0 = T * 8 + 2 * tig;
      gp[(size_t)b0 * 512 + t0]           = sacc[m * 16 + T * 4 + 0];
      gp[(size_t)(b0 + 1) * 512 + t0]     = sacc[m * 16 + T * 4 + 1];
      gp[(size_t)b0 * 512 + t0 + 8]       = sacc[m * 16 + T * 4 + 2];
      gp[(size_t)(b0 + 1) * 512 + t0 + 8] = sacc[m * 16 + T * 4 + 3];
    }
  if (PASS >= 1 && ln == 0) {
    g_zpart[bid * 32 + 2 * w]     = accz0;
    g_zpart[bid * 32 + 2 * w + 1] = accz1;
  }
}

// ---------------- parallel partial reduction (4 threads / element) --------
template <bool WITH_Z>
__global__ void reduce_kernel() {
  __shared__ float red[512];
  __shared__ float zs[256];
  const int tid = threadIdx.x;
  const int sub = tid >> 7;            // 0..3, 38 partials each
  const int el = tid & 127;
  const int elem = blockIdx.x * 128 + el;

  float s = 0.f;
  const int p0 = sub * 38;
#pragma unroll 4
  for (int i = 0; i < 38; i++)
    s += g_spart[(size_t)(p0 + i) * ELEMS + elem];
  red[tid] = s;
  __syncthreads();
  if (sub == 0)
    g_sred[elem] = red[el] + red[128 + el] + red[256 + el] + red[384 + el];

  if (WITH_Z && blockIdx.x == 0) {
    if (tid < 256) {
      const int u = tid & 31, g = tid >> 5;
      float z = 0.f;
#pragma unroll 4
      for (int i = 0; i < 19; i++) z += g_zpart[(g * 19 + i) * 32 + u];
      zs[tid] = z;
    }
    __syncthreads();
    if (tid < 32) {
      float z = 0.f;
#pragma unroll
      for (int g = 0; g < 8; g++) z += zs[g * 32 + tid];
      g_zred[tid] = z;
    }
  }
}

// ---------------- squash --------------------------------------------------
template <int ZMODE, bool FINAL>
__global__ void squash_kernel(float* __restrict__ out) {
  const int gw = blockIdx.x * (blockDim.x >> 5) + (threadIdx.x >> 5);
  const int lane = threadIdx.x & 31;   // = u
  if (gw >= 512) return;
  const int b = gw >> 4, k = gw & 15;
  const int idx = (b * 32 + lane) * 16 + k;

  float s = g_sred[idx];
  const float Z = (ZMODE == 1) ? 8192.f : g_zred[lane];
  s /= Z;

  float msq = s * s;
#pragma unroll
  for (int o = 16; o > 0; o >>= 1) msq += __shfl_xor_sync(0xffffffffu, msq, o);

  const float v = (msq / (1.f + msq)) * s * rsqrtf(msq);
  if (FINAL) out[idx] = v;
  else       g_v[idx] = v;
}

extern "C" void kernel_launch(void* const* d_in, const int* in_sizes, int n_in,
                              void* d_out, int out_size) {
  const float* x = (const float*)d_in[0];   // (32,16,8192)
  const float* W = (const float*)d_in[1];   // (8192,32,16,16)
  if (n_in >= 2 && in_sizes[0] > in_sizes[1]) {
    const float* tmp = x; x = W; W = tmp;
  }
  float* out = (float*)d_out;

  // iter 1: W->fp16 scratch + s~1 -> v1
  gemm_kernel<0><<<NSTRIPE, 512>>>(x, W);
  reduce_kernel<false><<<128, 512>>>();
  squash_kernel<1, false><<<16, 1024>>>(nullptr);
  // iter 2: recompute u_hat, b1 = a1, weighted s~2 -> v2
  gemm_kernel<1><<<NSTRIPE, 512>>>(x, W);
  reduce_kernel<true><<<128, 512>>>();
  squash_kernel<2, false><<<16, 1024>>>(nullptr);
  // iter 3: recompute u_hat, b2 = b1 + a2, weighted s~3 -> v3 (output)
  gemm_kernel<2><<<NSTRIPE, 512>>>(x, W);
  reduce_kernel<true><<<128, 512>>>();
  squash_kernel<2, true><<<16, 1024>>>(out);
}

// round 15
// speedup vs baseline: 1.3702x; 1.3702x over previous
#include <cuda_runtime.h>
#include <cuda_fp16.h>
#include <cstddef>

// Digits_Caps dynamic routing. B=32, C=8192, U=32, K=16, I=16, 3 iters.
// Unified HMMA GEMM kernel, 3 passes over channels:
//  PASS 0: read W fp32, write W fp16 scratch, s~1 = sum_c u_hat (HMMA)
//  PASS 1: recompute u_hat from fp16 W (cp.async staged), a->b (write bij), s~2
//  PASS 2: same but b_old from bij (no write), s~3
// u_hat never materialized. PASS1/2 stage W via zero-register cp.async
// double buffers (fixes R12's register-spill bind at regs=128).

#define NSTRIPE 152
#define ELEMS 16384   // B*U*K

// fp16 W scratch: [(c*16+w)*128 + f] 8-byte units = 128 MB
static __device__ uint2 g_w16[(size_t)8192 * 16 * 128];
static __device__ float g_spart[NSTRIPE * ELEMS];
static __device__ float g_zpart[NSTRIPE * 32];
static __device__ float g_sred[ELEMS];
static __device__ float g_zred[32];
static __device__ float g_v[ELEMS];
static __device__ float g_bij[8192 * 32];

__device__ __forceinline__ unsigned packh2(float lo, float hi) {
  unsigned r;
  asm("cvt.rn.f16x2.f32 %0, %1, %2;" : "=r"(r) : "f"(hi), "f"(lo));
  return r;
}
__device__ __forceinline__ unsigned smem_u32(const void* p) {
  unsigned a;
  asm("{ .reg .u64 t; cvta.to.shared.u64 t, %1; cvt.u32.u64 %0, t; }"
      : "=r"(a) : "l"(p));
  return a;
}
__device__ __forceinline__ void sts64(unsigned addr, unsigned p0, unsigned p1) {
  asm volatile("st.shared.v2.b32 [%0], {%1, %2};" :: "r"(addr), "r"(p0), "r"(p1));
}
__device__ __forceinline__ unsigned lds32(unsigned addr) {
  unsigned v;
  asm("ld.shared.b32 %0, [%1];" : "=r"(v) : "r"(addr));
  return v;
}
__device__ __forceinline__ void ldmatrix_x4(unsigned& r0, unsigned& r1,
                                            unsigned& r2, unsigned& r3,
                                            unsigned addr) {
  asm volatile("ldmatrix.sync.aligned.m8n8.x4.shared.b16 {%0,%1,%2,%3}, [%4];"
               : "=r"(r0), "=r"(r1), "=r"(r2), "=r"(r3) : "r"(addr));
}
__device__ __forceinline__ void mma16816(float& d0, float& d1, float& d2, float& d3,
                                         unsigned a0, unsigned a1, unsigned a2, unsigned a3,
                                         unsigned b0, unsigned b1) {
  asm volatile(
      "mma.sync.aligned.m16n8k16.row.col.f32.f16.f16.f32 "
      "{%0,%1,%2,%3}, {%4,%5,%6,%7}, {%8,%9}, {%10,%11,%12,%13};"
      : "=f"(d0), "=f"(d1), "=f"(d2), "=f"(d3)
      : "r"(a0), "r"(a1), "r"(a2), "r"(a3), "r"(b0), "r"(b1),
        "f"(0.f), "f"(0.f), "f"(0.f), "f"(0.f));
}
__device__ __forceinline__ void cpasync8(unsigned dst, const void* src) {
  asm volatile("cp.async.ca.shared.global [%0], [%1], 8;" :: "r"(dst), "l"(src));
}
__device__ __forceinline__ void cpasync_commit() {
  asm volatile("cp.async.commit_group;");
}
template <int N>
__device__ __forceinline__ void cpasync_wait() {
  asm volatile("cp.async.wait_group %0;" :: "n"(N));
}
// warp sum via butterfly (redux.f32 not supported on sm_103)
__device__ __forceinline__ float warp_sum(float v) {
#pragma unroll
  for (int o = 16; o > 0; o >>= 1)
    v += __shfl_xor_sync(0xffffffffu, v, o);
  return v;
}
// pairwise tree dot of 16 terms
__device__ __forceinline__ float dot16(const float* a, const float* b) {
  float q0 = fmaf(a[1], b[1], a[0] * b[0]);
  float q1 = fmaf(a[3], b[3], a[2] * b[2]);
  float q2 = fmaf(a[5], b[5], a[4] * b[4]);
  float q3 = fmaf(a[7], b[7], a[6] * b[6]);
  float q4 = fmaf(a[9], b[9], a[8] * b[8]);
  float q5 = fmaf(a[11], b[11], a[10] * b[10]);
  float q6 = fmaf(a[13], b[13], a[12] * b[12]);
  float q7 = fmaf(a[15], b[15], a[14] * b[14]);
  q0 += q4; q1 += q5; q2 += q6; q3 += q7;
  q0 += q2; q1 += q3;
  return q0 + q1;
}

// smem: x16 [j=0..7][b rows of 48B] then per-warp W16 double buffers (2x 32t x 48B)
#define XCH 1536
#define WAOFF 12288
#define WBUF 1536
#define SM_TOT (WAOFF + 16 * 2 * WBUF)   // 61440 B (static)

// ---------------- unified GEMM + routing pass -----------------------------
template <int PASS>
__global__ __launch_bounds__(512, 1) void gemm_kernel(
    const float* __restrict__ x, const float* __restrict__ W) {
  __shared__ __align__(128) char sm[SM_TOT];
  const int t = threadIdx.x;
  const int w = t >> 5;            // warp 0..15, owns t-range [w*32, w*32+32)
  const int ln = t & 31;
  const int gid = ln >> 2;         // 0..7
  const int tig = ln & 3;          // 0..3
  const int bid = blockIdx.x;

  const unsigned xb = smem_u32(sm);
  const unsigned wb0 = xb + WAOFF + w * (2 * WBUF);
  const unsigned wb1 = wb0 + WBUF;

  const unsigned lrow = (ln & 7) + ((ln >> 3) & 1) * 8;
  const unsigned lcol = (ln >> 4) * 16;

  float sacc[32];
#pragma unroll
  for (int p = 0; p < 32; p++) sacc[p] = 0.f;
  float accz0 = 0.f, accz1 = 0.f;

  // v in registers (PASS>=1): vv[m*16+T*4+q] matching d-fragment layout
  float vv[32];
  if (PASS >= 1) {
#pragma unroll
    for (int m = 0; m < 2; m++)
#pragma unroll
      for (int T = 0; T < 4; T++) {
        const int t0 = w * 32 + m * 16 + gid;
        const int b0 = T * 8 + 2 * tig;
        vv[m * 16 + T * 4 + 0] = g_v[(size_t)b0 * 512 + t0];
        vv[m * 16 + T * 4 + 1] = g_v[(size_t)(b0 + 1) * 512 + t0];
        vv[m * 16 + T * 4 + 2] = g_v[(size_t)b0 * 512 + t0 + 8];
        vv[m * 16 + T * 4 + 3] = g_v[(size_t)(b0 + 1) * 512 + t0 + 8];
      }
  }

  // ---- W staging -----------------------------------------------------------
  // PASS>=1: zero-register cp.async from packed g_w16 into warp-private buffer
  auto stage_async = [&](unsigned buf, int c) {
    const char* src = (const char*)(g_w16 + ((size_t)c * 16 + w) * 128);
#pragma unroll
    for (int r = 0; r < 4; r++) {
      const int f = ln + r * 32;
      cpasync8(buf + (f >> 2) * 48 + (f & 3) * 8, src + f * 8);
    }
    cpasync_commit();
  };
  // PASS 0: register path (fp32 LDG -> cvt -> STS), also writes g_w16
  auto stage_p0 = [&](unsigned buf, int c) {
    const float4* src = (const float4*)(W + (size_t)c * 8192 + w * 512);
    uint2* dst = g_w16 + ((size_t)c * 16 + w) * 128;
#pragma unroll
    for (int r = 0; r < 4; r++) {
      const float4 v = src[ln + r * 32];
      const unsigned p0 = packh2(v.x, v.y);
      const unsigned p1 = packh2(v.z, v.w);
      uint2 o; o.x = p0; o.y = p1;
      dst[ln + r * 32] = o;
      const int f = ln + r * 32;
      sts64(buf + (f >> 2) * 48 + (f & 3) * 8, p0, p1);
    }
  };

  // preload first channel into buf0
  if (PASS == 0) stage_p0(wb0, bid * 8);
  else           stage_async(wb0, bid * 8);
  int par = 0;

  for (int chunk = bid; chunk < 1024; chunk += NSTRIPE) {
    __syncthreads();   // previous chunk's compute done with x16
    const int cbase = chunk * 8;
#pragma unroll
    for (int r = 0; r < 8; r++) {
      const int e = t + r * 512;
      const int j = e & 7, bi = e >> 3;
      const int i = bi & 15, b = bi >> 4;
      const float v = x[(size_t)bi * 8192 + cbase + j];
      *(__half*)(sm + j * XCH + b * 48 + i * 2) = __float2half(v);
    }
    __syncthreads();

#pragma unroll 1
    for (int j = 0; j < 8; j++) {
      const int c = cbase + j;
      const int cn = (j < 7) ? (c + 1) : (chunk + NSTRIPE) * 8;
      const unsigned wcur = par ? wb1 : wb0;
      const unsigned wnxt = par ? wb0 : wb1;

      if (PASS >= 1) {
        // issue next channel's stage, then ensure current has landed
        if (cn < 8192) { stage_async(wnxt, cn); cpasync_wait<1>(); }
        else           { cpasync_wait<0>(); }
        __syncwarp();
      }

      float bold0 = 0.f, bold1 = 0.f;
      if (PASS == 2) {
        bold0 = g_bij[c * 32 + 2 * w];
        bold1 = g_bij[c * 32 + 2 * w + 1];
      }

      // B fragments from x16[j]
      unsigned bf[8];
#pragma unroll
      for (int T = 0; T < 4; T++) {
        const unsigned ba = xb + j * XCH + (T * 8 + gid) * 48 + tig * 4;
        bf[2 * T]     = lds32(ba);
        bf[2 * T + 1] = lds32(ba + 16);
      }

      // both m-tiles' MMAs up front (ILP-2 routing chains)
      float dm0[16], dm1[16];
      {
        unsigned a0, a1, a2, a3;
        ldmatrix_x4(a0, a1, a2, a3, wcur + lrow * 48 + lcol);
#pragma unroll
        for (int T = 0; T < 4; T++)
          mma16816(dm0[T * 4], dm0[T * 4 + 1], dm0[T * 4 + 2], dm0[T * 4 + 3],
                   a0, a1, a2, a3, bf[2 * T], bf[2 * T + 1]);
        ldmatrix_x4(a0, a1, a2, a3, wcur + (16 + lrow) * 48 + lcol);
#pragma unroll
        for (int T = 0; T < 4; T++)
          mma16816(dm1[T * 4], dm1[T * 4 + 1], dm1[T * 4 + 2], dm1[T * 4 + 3],
                   a0, a1, a2, a3, bf[2 * T], bf[2 * T + 1]);
      }

      if (PASS == 0) {
#pragma unroll
        for (int p = 0; p < 16; p++) sacc[p] += dm0[p];
#pragma unroll
        for (int p = 0; p < 16; p++) sacc[16 + p] += dm1[p];
        // stage next channel (register path) into the now-free buffer
        if (cn < 8192) stage_p0(wnxt, cn);
        __syncwarp();
      } else {
        // two overlapped short chains: tree-dot -> butterfly -> exp
        const float part0 = dot16(dm0, vv);
        const float part1 = dot16(dm1, vv + 16);
        const float r0 = warp_sum(part0);
        const float r1 = warp_sum(part1);
        const float a0v = r0 * (1.f / 32.f);
        const float a1v = r1 * (1.f / 32.f);
        const float bnew0 = (PASS == 1) ? a0v : (bold0 + a0v);
        const float bnew1 = (PASS == 1) ? a1v : (bold1 + a1v);
        if (PASS == 1 && ln == 0) {
          g_bij[c * 32 + 2 * w]     = bnew0;
          g_bij[c * 32 + 2 * w + 1] = bnew1;
        }
        const float wt0 = __expf(bnew0);
        const float wt1 = __expf(bnew1);
        accz0 += wt0; accz1 += wt1;
#pragma unroll
        for (int p = 0; p < 16; p++) sacc[p] = fmaf(wt0, dm0[p], sacc[p]);
#pragma unroll
        for (int p = 0; p < 16; p++) sacc[16 + p] = fmaf(wt1, dm1[p], sacc[16 + p]);
      }

      par ^= 1;
    }
  }

  // s~ partials -> g_spart[bid][b*512 + t]
  float* gp = g_spart + (size_t)bid * ELEMS;
#pragma unroll
  for (int m = 0; m < 2; m++)
#pragma unroll
    for (int T = 0; T < 4; T++) {
      const int t0 = w * 32 + m * 16 + gid;
      const int b0 = T * 8 + 2 * tig;
      gp[(size_t)b0 * 512 + t0]           = sacc[m * 16 + T * 4 + 0];
      gp[(size_t)(b0 + 1) * 512 + t0]     = sacc[m * 16 + T * 4 + 1];
      gp[(size_t)b0 * 512 + t0 + 8]       = sacc[m * 16 + T * 4 + 2];
      gp[(size_t)(b0 + 1) * 512 + t0 + 8] = sacc[m * 16 + T * 4 + 3];
    }
  if (PASS >= 1 && ln == 0) {
    g_zpart[bid * 32 + 2 * w]     = accz0;
    g_zpart[bid * 32 + 2 * w + 1] = accz1;
  }
}

// ---------------- parallel partial reduction (4 threads / element) --------
template <bool WITH_Z>
__global__ void reduce_kernel() {
  __shared__ float red[512];
  __shared__ float zs[256];
  const int tid = threadIdx.x;
  const int sub = tid >> 7;            // 0..3, 38 partials each
  const int el = tid & 127;
  const int elem = blockIdx.x * 128 + el;

  float s = 0.f;
  const int p0 = sub * 38;
#pragma unroll 4
  for (int i = 0; i < 38; i++)
    s += g_spart[(size_t)(p0 + i) * ELEMS + elem];
  red[tid] = s;
  __syncthreads();
  if (sub == 0)
    g_sred[elem] = red[el] + red[128 + el] + red[256 + el] + red[384 + el];

  if (WITH_Z && blockIdx.x == 0) {
    if (tid < 256) {
      const int u = tid & 31, g = tid >> 5;
      float z = 0.f;
#pragma unroll 4
      for (int i = 0; i < 19; i++) z += g_zpart[(g * 19 + i) * 32 + u];
      zs[tid] = z;
    }
    __syncthreads();
    if (tid < 32) {
      float z = 0.f;
#pragma unroll
      for (int g = 0; g < 8; g++) z += zs[g * 32 + tid];
      g_zred[tid] = z;
    }
  }
}

// ---------------- squash --------------------------------------------------
template <int ZMODE, bool FINAL>
__global__ void squash_kernel(float* __restrict__ out) {
  const int gw = blockIdx.x * (blockDim.x >> 5) + (threadIdx.x >> 5);
  const int lane = threadIdx.x & 31;   // = u
  if (gw >= 512) return;
  const int b = gw >> 4, k = gw & 15;
  const int idx = (b * 32 + lane) * 16 + k;

  float s = g_sred[idx];
  const float Z = (ZMODE == 1) ? 8192.f : g_zred[lane];
  s /= Z;

  float msq = s * s;
#pragma unroll
  for (int o = 16; o > 0; o >>= 1) msq += __shfl_xor_sync(0xffffffffu, msq, o);

  const float v = (msq / (1.f + msq)) * s * rsqrtf(msq);
  if (FINAL) out[idx] = v;
  else       g_v[idx] = v;
}

extern "C" void kernel_launch(void* const* d_in, const int* in_sizes, int n_in,
                              void* d_out, int out_size) {
  const float* x = (const float*)d_in[0];   // (32,16,8192)
  const float* W = (const float*)d_in[1];   // (8192,32,16,16)
  if (n_in >= 2 && in_sizes[0] > in_sizes[1]) {
    const float* tmp = x; x = W; W = tmp;
  }
  float* out = (float*)d_out;

  // iter 1: W->fp16 scratch + s~1 -> v1
  gemm_kernel<0><<<NSTRIPE, 512>>>(x, W);
  reduce_kernel<false><<<128, 512>>>();
  squash_kernel<1, false><<<16, 1024>>>(nullptr);
  // iter 2: recompute u_hat, b1 = a1, weighted s~2 -> v2
  gemm_kernel<1><<<NSTRIPE, 512>>>(x, W);
  reduce_kernel<true><<<128, 512>>>();
  squash_kernel<2, false><<<16, 1024>>>(nullptr);
  // iter 3: recompute u_hat, b2 = b1 + a2, weighted s~3 -> v3 (output)
  gemm_kernel<2><<<NSTRIPE, 512>>>(x, W);
  reduce_kernel<true><<<128, 512>>>();
  squash_kernel<2, true><<<16, 1024>>>(out);
}